// round 5
// baseline (speedup 1.0000x reference)
#include <cuda_runtime.h>
#include <cuda_bf16.h>

typedef unsigned int u32; typedef unsigned long long u64;
#define Mmol  2048
#define Aat   24
#define Nnode (Mmol*Aat)
#define EPM   576            // real edge rows per molecule (incl diag)
#define EPMP  640            // padded to 5 tiles of 128
#define PIT   272            // smem row pitch bytes (136 bf16) -> conflict-free ldmatrix
#define IMG   34816          // 128 rows * 272 B

// ---------------- device scratch (no allocation allowed) ----------------
__device__ float g_EA [(size_t)Mmol*EPMP*128];   // ~671 MB
__device__ float g_h  [(size_t)Nnode*128];
__device__ float g_x  [(size_t)Nnode*128];
__device__ float g_agg[(size_t)Nnode*128];
__device__ __align__(16) unsigned char g_Wimg[5][2][32768]; // [nlw,ew1,ew2,nw1,nw2][hi,lo], [k][n] bf16 dense

// ---------------- helpers ----------------
__device__ __forceinline__ u32 smaddr(const void* p){
    u32 a; asm("{ .reg .u64 t; cvta.to.shared.u64 t, %1; cvt.u32.u64 %0, t; }" : "=r"(a) : "l"(p)); return a;
}
__device__ __forceinline__ float ssp(float x){
    return fmaxf(x, 0.f) + __logf(1.f + __expf(-fabsf(x))) - 0.6931471805599453f;
}
__device__ __forceinline__ void cpa16(u32 dst, const void* src){
    asm volatile("cp.async.cg.shared.global [%0], [%1], 16;" :: "r"(dst), "l"(src) : "memory");
}
#define CP_COMMIT asm volatile("cp.async.commit_group;" ::: "memory")
#define CP_WAIT0  asm volatile("cp.async.wait_group 0;"  ::: "memory")

__device__ __forceinline__ void ldsm4(u32* r, u32 a){
    asm volatile("ldmatrix.sync.aligned.m8n8.x4.shared.b16 {%0,%1,%2,%3}, [%4];"
        : "=r"(r[0]),"=r"(r[1]),"=r"(r[2]),"=r"(r[3]) : "r"(a));
}
__device__ __forceinline__ void ldsm4t(u32* r, u32 a){
    asm volatile("ldmatrix.sync.aligned.m8n8.x4.trans.shared.b16 {%0,%1,%2,%3}, [%4];"
        : "=r"(r[0]),"=r"(r[1]),"=r"(r[2]),"=r"(r[3]) : "r"(a));
}
__device__ __forceinline__ void mma_bf(float* d, const u32* a, u32 b0, u32 b1){
    asm volatile("mma.sync.aligned.m16n8k16.row.col.f32.bf16.bf16.f32 "
        "{%0,%1,%2,%3}, {%4,%5,%6,%7}, {%8,%9}, {%0,%1,%2,%3};"
        : "+f"(d[0]),"+f"(d[1]),"+f"(d[2]),"+f"(d[3])
        : "r"(a[0]),"r"(a[1]),"r"(a[2]),"r"(a[3]),"r"(b0),"r"(b1));
}

// stage this warp's 16-row band: fp32 gmem rows -> hi/lo bf16 smem images (pitch 272)
__device__ __forceinline__ void stage_band(const float* __restrict__ src, char* Ah, char* Al, int R, int lane){
    #pragma unroll 4
    for (int i = 0; i < 16; ++i){
        int row = R + i;
        float4 v = ((const float4*)src)[row*32 + lane];
        __nv_bfloat162 h0 = __floats2bfloat162_rn(v.x, v.y);
        __nv_bfloat162 h1 = __floats2bfloat162_rn(v.z, v.w);
        __nv_bfloat162 l0 = __floats2bfloat162_rn(v.x-__bfloat162float(h0.x), v.y-__bfloat162float(h0.y));
        __nv_bfloat162 l1 = __floats2bfloat162_rn(v.z-__bfloat162float(h1.x), v.w-__bfloat162float(h1.y));
        int o = row*PIT + lane*8;
        *(uint2*)(Ah+o) = make_uint2(*(u32*)&h0, *(u32*)&h1);
        *(uint2*)(Al+o) = make_uint2(*(u32*)&l0, *(u32*)&l1);
    }
}

// 16x128 (rows R..R+15) D = A(16x128) * B(128x128), 3-term bf16 emulation.
__device__ __forceinline__ void wgemm3(float acc[16][4], u32 baseAh, u32 baseAl,
                                       u32 baseBh, u32 baseBl, int lane){
    u32 off = (lane & 15)*PIT + (lane >> 4)*16;
    #pragma unroll
    for (int ks = 0; ks < 8; ++ks){
        u32 ah[4], al[4];
        ldsm4(ah, baseAh + off + ks*32);
        ldsm4(al, baseAl + off + ks*32);
        #pragma unroll
        for (int nb = 0; nb < 8; ++nb){
            u32 bh[4], bl[4];
            u32 ba = off + ks*(16*PIT) + nb*32;
            ldsm4t(bh, baseBh + ba);
            ldsm4t(bl, baseBl + ba);
            mma_bf(acc[nb*2],   ah, bh[0], bh[1]);
            mma_bf(acc[nb*2],   ah, bl[0], bl[1]);
            mma_bf(acc[nb*2],   al, bh[0], bh[1]);
            mma_bf(acc[nb*2+1], ah, bh[2], bh[3]);
            mma_bf(acc[nb*2+1], ah, bl[2], bl[3]);
            mma_bf(acc[nb*2+1], al, bh[2], bh[3]);
        }
    }
}
__device__ __forceinline__ void zacc(float acc[16][4]){
    #pragma unroll
    for (int i=0;i<16;++i){ acc[i][0]=0.f; acc[i][1]=0.f; acc[i][2]=0.f; acc[i][3]=0.f; }
}
// mid = ssp(acc + b1) -> hi/lo images (overwrites own A band)
__device__ __forceinline__ void write_mid(const float acc[16][4], const float* b1s,
                                          char* Ah, char* Al, int R, int lane){
    int r0 = R + (lane>>2);
    int cb = (lane&3)*2;
    #pragma unroll
    for (int nb = 0; nb < 16; ++nb){
        int c = nb*8 + cb;
        float bx = b1s[c], by = b1s[c+1];
        float f0 = ssp(acc[nb][0]+bx), f1 = ssp(acc[nb][1]+by);
        float f2 = ssp(acc[nb][2]+bx), f3 = ssp(acc[nb][3]+by);
        __nv_bfloat162 h0 = __floats2bfloat162_rn(f0,f1);
        __nv_bfloat162 l0 = __floats2bfloat162_rn(f0-__bfloat162float(h0.x), f1-__bfloat162float(h0.y));
        __nv_bfloat162 h1 = __floats2bfloat162_rn(f2,f3);
        __nv_bfloat162 l1 = __floats2bfloat162_rn(f2-__bfloat162float(h1.x), f3-__bfloat162float(h1.y));
        *(u32*)(Ah + r0*PIT + c*2)     = *(u32*)&h0;
        *(u32*)(Al + r0*PIT + c*2)     = *(u32*)&l0;
        *(u32*)(Ah + (r0+8)*PIT + c*2) = *(u32*)&h1;
        *(u32*)(Al + (r0+8)*PIT + c*2) = *(u32*)&l1;
    }
}

// ---------------- one-time prep / init ----------------
__global__ void k_prep(const float* nlw, const float* ew1, const float* ew2,
                       const float* nw1, const float* nw2){
    const float* srcs[5] = {nlw, ew1, ew2, nw1, nw2};
    const float* src = srcs[blockIdx.x];
    int n = threadIdx.x;
    for (int k = 0; k < 128; ++k){
        float v = src[k*128 + n];
        __nv_bfloat16 h = __float2bfloat16_rn(v);
        __nv_bfloat16 l = __float2bfloat16_rn(v - __bfloat162float(h));
        *(__nv_bfloat16*)(g_Wimg[blockIdx.x][0] + k*256 + n*2) = h;
        *(__nv_bfloat16*)(g_Wimg[blockIdx.x][1] + k*256 + n*2) = l;
    }
}
__global__ void k_init_h(const int* __restrict__ charges, const float* __restrict__ emb){
    int idx = blockIdx.x*256 + threadIdx.x;
    g_h[idx] = emb[charges[idx>>7]*128 + (idx & 127)];
}
__global__ void k_init_ea(const float* __restrict__ coords){
    int w = (blockIdx.x*256 + threadIdx.x) >> 5;    // one warp per real edge row
    int lane = threadIdx.x & 31;
    int m = w / EPM, rr = w % EPM;
    int d = rr / Aat, s = rr % Aat;
    int ns = m*Aat + s, nd = m*Aat + d;
    float dx = coords[ns*3+0] - coords[nd*3+0];
    float dy = coords[ns*3+1] - coords[nd*3+1];
    float dz = coords[ns*3+2] - coords[nd*3+2];
    float dist = sqrtf(dx*dx + dy*dy + dz*dz);
    float* row = g_EA + ((size_t)m*EPMP + rr)*128;
    ((float4*)row)[lane] = make_float4(0.f,0.f,0.f,0.f);
    __syncwarp();
    const float delta = 10.0f/127.0f, inv = 127.0f/10.0f;
    const float coeff = -0.5f/(delta*delta);
    int g0 = max(0, (int)ceilf((dist - 1.09f)*inv));
    int g1 = min(127, (int)floorf((dist + 1.09f)*inv));
    int g = g0 + lane;
    if (g <= g1) { float od = dist - delta*(float)g; row[g] = __expf(coeff*od*od); }
}

// ---------------- x = h @ nlw ----------------
__global__ void __launch_bounds__(256,1) k_x_mma(){
    extern __shared__ __align__(16) char sm[];
    char *Wh = sm, *Wl = sm+IMG, *Ah = sm+2*IMG, *Al = sm+3*IMG;
    const int tid = threadIdx.x, wid = tid>>5, lane = tid&31, R = wid*16;
    for (int i = tid; i < 2048; i += 256){
        int k = i>>4, ch = i&15; u32 d = k*PIT + ch*16;
        cpa16(smaddr(Wh)+d, g_Wimg[0][0]+i*16);
        cpa16(smaddr(Wl)+d, g_Wimg[0][1]+i*16);
    }
    CP_COMMIT; CP_WAIT0; __syncthreads();
    size_t rowbase = (size_t)blockIdx.x * 128;
    stage_band(g_h + rowbase*128, Ah, Al, R, lane);
    __syncwarp();
    float acc[16][4]; zacc(acc);
    wgemm3(acc, smaddr(Ah)+R*PIT, smaddr(Al)+R*PIT, smaddr(Wh), smaddr(Wl), lane);
    int r0 = (int)rowbase + R + (lane>>2);
    int cb = (lane&3)*2;
    #pragma unroll
    for (int nb = 0; nb < 16; ++nb){
        int c = nb*8 + cb;
        *(float2*)(g_x + (size_t)r0*128 + c)     = make_float2(acc[nb][0], acc[nb][1]);
        *(float2*)(g_x + (size_t)(r0+8)*128 + c) = make_float2(acc[nb][2], acc[nb][3]);
    }
}

// ---------------- edge kernel (per molecule) ----------------
__global__ void __launch_bounds__(256,1) k_edge_mma(const float* __restrict__ eb1, const float* __restrict__ eb2){
    extern __shared__ __align__(16) char sm[];
    char *W1h = sm, *W1l = sm+IMG, *W2h = sm+2*IMG, *W2l = sm+3*IMG;
    char *Ah = sm+4*IMG, *Al = sm+5*IMG;
    float* xs  = (float*)(sm + 6*IMG);              // 24 x 129 floats
    float* b1s = (float*)(sm + 6*IMG + 12384);
    float* b2s = b1s + 128;
    const int tid = threadIdx.x, m = blockIdx.x;
    const int wid = tid>>5, lane = tid&31, R = wid*16;

    for (int i = tid; i < 2048; i += 256){
        int k = i>>4, ch = i&15; u32 d = k*PIT + ch*16;
        cpa16(smaddr(W1h)+d, g_Wimg[1][0]+i*16);
        cpa16(smaddr(W1l)+d, g_Wimg[1][1]+i*16);
        cpa16(smaddr(W2h)+d, g_Wimg[2][0]+i*16);
        cpa16(smaddr(W2l)+d, g_Wimg[2][1]+i*16);
    }
    CP_COMMIT;
    for (int i = tid; i < Aat*128; i += 256) xs[(i>>7)*129 + (i&127)] = g_x[(size_t)m*Aat*128 + i];
    if (tid < 128){ b1s[tid] = eb1[tid]; b2s[tid] = eb2[tid]; }
    CP_WAIT0; __syncthreads();

    float* eaBase = g_EA + (size_t)m*EPMP*128;
    u32 aAh = smaddr(Ah)+R*PIT, aAl = smaddr(Al)+R*PIT;
    u32 bW1h = smaddr(W1h), bW1l = smaddr(W1l), bW2h = smaddr(W2h), bW2l = smaddr(W2l);

    for (int t = 0; t < 5; ++t){
        stage_band(eaBase + (size_t)t*128*128, Ah, Al, R, lane);
        __syncwarp();
        float acc[16][4]; zacc(acc);
        wgemm3(acc, aAh, aAl, bW1h, bW1l, lane);
        write_mid(acc, b1s, Ah, Al, R, lane);
        __syncwarp();
        zacc(acc);
        wgemm3(acc, aAh, aAl, bW2h, bW2l, lane);
        // epilogue: +b2, * x[s], store fp32 EA (skip pad rows)
        int r0 = t*128 + R + (lane>>2);
        int cb = (lane&3)*2;
        int s0 = r0 % Aat, s1 = (r0+8) % Aat;
        bool ok0 = r0 < EPM, ok1 = (r0+8) < EPM;
        #pragma unroll
        for (int nb = 0; nb < 16; ++nb){
            int c = nb*8 + cb;
            float bx = b2s[c], by = b2s[c+1];
            if (ok0){
                float2 o = make_float2((acc[nb][0]+bx)*xs[s0*129+c], (acc[nb][1]+by)*xs[s0*129+c+1]);
                *(float2*)(eaBase + (size_t)r0*128 + c) = o;
            }
            if (ok1){
                float2 o = make_float2((acc[nb][2]+bx)*xs[s1*129+c], (acc[nb][3]+by)*xs[s1*129+c+1]);
                *(float2*)(eaBase + (size_t)(r0+8)*128 + c) = o;
            }
        }
    }
    __syncthreads();
    // agg[d][j] = sum_{s != d} EA[d*24+s][j]   (L2-hot, just written)
    float* aggBase = g_agg + (size_t)m*Aat*128;
    for (int o = tid; o < Aat*128; o += 256){
        int d = o >> 7, j = o & 127;
        const float* col = eaBase + (size_t)d*Aat*128 + j;
        float ssum = 0.f;
        #pragma unroll
        for (int s2 = 0; s2 < Aat; ++s2) ssum += col[s2*128];
        aggBase[o] = ssum - col[d*128];
    }
}

// ---------------- node kernel: h += ssp(agg@n_w1+b1)@n_w2+b2 ----------------
__global__ void __launch_bounds__(256,1) k_node_mma(const float* __restrict__ nb1, const float* __restrict__ nb2){
    extern __shared__ __align__(16) char sm[];
    char *W1h = sm, *W1l = sm+IMG, *W2h = sm+2*IMG, *W2l = sm+3*IMG;
    char *Ah = sm+4*IMG, *Al = sm+5*IMG;
    float* b1s = (float*)(sm + 6*IMG);
    float* b2s = b1s + 128;
    const int tid = threadIdx.x, wid = tid>>5, lane = tid&31, R = wid*16;

    for (int i = tid; i < 2048; i += 256){
        int k = i>>4, ch = i&15; u32 d = k*PIT + ch*16;
        cpa16(smaddr(W1h)+d, g_Wimg[3][0]+i*16);
        cpa16(smaddr(W1l)+d, g_Wimg[3][1]+i*16);
        cpa16(smaddr(W2h)+d, g_Wimg[4][0]+i*16);
        cpa16(smaddr(W2l)+d, g_Wimg[4][1]+i*16);
    }
    CP_COMMIT;
    if (tid < 128){ b1s[tid] = nb1[tid]; b2s[tid] = nb2[tid]; }
    CP_WAIT0; __syncthreads();

    size_t rowbase = (size_t)blockIdx.x * 128;
    stage_band(g_agg + rowbase*128, Ah, Al, R, lane);
    __syncwarp();
    float acc[16][4]; zacc(acc);
    wgemm3(acc, smaddr(Ah)+R*PIT, smaddr(Al)+R*PIT, smaddr(W1h), smaddr(W1l), lane);
    write_mid(acc, b1s, Ah, Al, R, lane);
    __syncwarp();
    zacc(acc);
    wgemm3(acc, smaddr(Ah)+R*PIT, smaddr(Al)+R*PIT, smaddr(W2h), smaddr(W2l), lane);

    int r0 = (int)rowbase + R + (lane>>2);
    int cb = (lane&3)*2;
    #pragma unroll
    for (int nb = 0; nb < 16; ++nb){
        int c = nb*8 + cb;
        float bx = b2s[c], by = b2s[c+1];
        float2 h0 = *(float2*)(g_h + (size_t)r0*128 + c);
        float2 h1 = *(float2*)(g_h + (size_t)(r0+8)*128 + c);
        h0.x += acc[nb][0] + bx;  h0.y += acc[nb][1] + by;
        h1.x += acc[nb][2] + bx;  h1.y += acc[nb][3] + by;
        *(float2*)(g_h + (size_t)r0*128 + c)     = h0;
        *(float2*)(g_h + (size_t)(r0+8)*128 + c) = h1;
    }
}

// ---------------- graph readout ----------------
__global__ void __launch_bounds__(256) k_graph(const float* __restrict__ gw1, const float* __restrict__ gb1,
                                               const float* __restrict__ gw2, const float* __restrict__ gb2,
                                               float* __restrict__ out)
{
    __shared__ float hs[Aat*128];
    __shared__ float w1s[128*64];
    __shared__ float red[256];
    const int tid = threadIdx.x, m = blockIdx.x;
    {
        const float4* hg = (const float4*)(g_h + (size_t)m*Aat*128);
        for (int i = tid; i < 768; i += 256) ((float4*)hs)[i] = hg[i];
        const float4* wg = (const float4*)gw1;
        for (int i = tid; i < 2048; i += 256) ((float4*)w1s)[i] = wg[i];
    }
    __syncthreads();
    float local = 0.f;
    for (int pos = tid; pos < Aat*64; pos += 256){
        int s = pos >> 6, c = pos & 63;
        float acc = gb1[c];
        #pragma unroll 16
        for (int k = 0; k < 128; ++k) acc += hs[s*128+k] * w1s[k*64+c];
        local += ssp(acc) * gw2[c];
    }
    red[tid] = local;
    __syncthreads();
    #pragma unroll
    for (int off = 128; off > 0; off >>= 1){
        if (tid < off) red[tid] += red[tid+off];
        __syncthreads();
    }
    if (tid == 0) out[m] = red[0] + (float)Aat * gb2[0];
}

// ---------------- launch ----------------
extern "C" void kernel_launch(void* const* d_in, const int* in_sizes, int n_in,
                              void* d_out, int out_size)
{
    const int*   charges = (const int*)  d_in[0];
    const float* coords  = (const float*)d_in[1];
    const float* emb = (const float*)d_in[4];
    const float* nlw = (const float*)d_in[5];
    const float* ew1 = (const float*)d_in[6];
    const float* eb1 = (const float*)d_in[7];
    const float* ew2 = (const float*)d_in[8];
    const float* eb2 = (const float*)d_in[9];
    const float* nw1 = (const float*)d_in[10];
    const float* nb1 = (const float*)d_in[11];
    const float* nw2 = (const float*)d_in[12];
    const float* nb2 = (const float*)d_in[13];
    const float* gw1 = (const float*)d_in[14];
    const float* gb1 = (const float*)d_in[15];
    const float* gw2 = (const float*)d_in[16];
    const float* gb2 = (const float*)d_in[17];
    float* out = (float*)d_out;

    const int SME = 6*IMG + 12384 + 1024;  // 222304
    const int SMN = 6*IMG + 1024;          // 209920
    const int SMX = 4*IMG;                 // 139264
    cudaFuncSetAttribute(k_edge_mma, cudaFuncAttributeMaxDynamicSharedMemorySize, SME);
    cudaFuncSetAttribute(k_node_mma, cudaFuncAttributeMaxDynamicSharedMemorySize, SMN);
    cudaFuncSetAttribute(k_x_mma,    cudaFuncAttributeMaxDynamicSharedMemorySize, SMX);

    k_prep<<<5, 128>>>(nlw, ew1, ew2, nw1, nw2);
    k_init_h <<<(Nnode*128)/256, 256>>>(charges, emb);
    k_init_ea<<<(Mmol*EPM)/8, 256>>>(coords);

    for (int l = 0; l < 4; ++l) {
        k_x_mma   <<<384,  256, SMX>>>();
        k_edge_mma<<<Mmol, 256, SME>>>(eb1, eb2);
        k_node_mma<<<384,  256, SMN>>>(nb1, nb2);
    }
    k_graph<<<Mmol, 256>>>(gw1, gb1, gw2, gb2, out);
}

// round 6
// speedup vs baseline: 1.1919x; 1.1919x over previous
#include <cuda_runtime.h>
#include <cuda_bf16.h>

typedef unsigned int u32; typedef unsigned long long u64;
#define Mmol 2048
#define Aat 24
#define Nnode (Mmol*Aat)
#define PIT 272
#define IMG 34816

// EA per (m,d): 8 ks-chunks of 512 u32: [hi mb0 |hi mb1 |lo mb0 |lo mb1], each 128 u32
__device__ u32   g_EAf[(size_t)Mmol*24*4096];
__device__ float g_h  [(size_t)Nnode*128];
__device__ float g_x  [(size_t)Nnode*128];
__device__ float g_agg[(size_t)Nnode*128];
__device__ __align__(16) unsigned char g_Wimg[5][2][32768];

__device__ __forceinline__ u32 smaddr(const void* p){
    u32 a; asm("{ .reg .u64 t; cvta.to.shared.u64 t, %1; cvt.u32.u64 %0, t; }" : "=r"(a) : "l"(p)); return a;
}
__device__ __forceinline__ float ssp(float x){
    return fmaxf(x, 0.f) + __logf(1.f + __expf(-fabsf(x))) - 0.6931471805599453f;
}
__device__ __forceinline__ void cpa16(u32 dst, const void* src){
    asm volatile("cp.async.cg.shared.global [%0], [%1], 16;" :: "r"(dst), "l"(src) : "memory");
}
#define CP_COMMIT asm volatile("cp.async.commit_group;" ::: "memory")
#define CP_WAIT0  asm volatile("cp.async.wait_group 0;"  ::: "memory")
__device__ __forceinline__ void ldsm4(u32* r, u32 a){
    asm volatile("ldmatrix.sync.aligned.m8n8.x4.shared.b16 {%0,%1,%2,%3}, [%4];"
        : "=r"(r[0]),"=r"(r[1]),"=r"(r[2]),"=r"(r[3]) : "r"(a));
}
__device__ __forceinline__ void ldsm4t(u32* r, u32 a){
    asm volatile("ldmatrix.sync.aligned.m8n8.x4.trans.shared.b16 {%0,%1,%2,%3}, [%4];"
        : "=r"(r[0]),"=r"(r[1]),"=r"(r[2]),"=r"(r[3]) : "r"(a));
}
__device__ __forceinline__ void mma_bf(float* d, const u32* a, u32 b0, u32 b1){
    asm volatile("mma.sync.aligned.m16n8k16.row.col.f32.bf16.bf16.f32 "
        "{%0,%1,%2,%3}, {%4,%5,%6,%7}, {%8,%9}, {%0,%1,%2,%3};"
        : "+f"(d[0]),"+f"(d[1]),"+f"(d[2]),"+f"(d[3])
        : "r"(a[0]),"r"(a[1]),"r"(a[2]),"r"(a[3]),"r"(b0),"r"(b1));
}
__device__ __forceinline__ void sp2(float x, float y, u32& h, u32& l){
    __nv_bfloat162 hb = __floats2bfloat162_rn(x, y);
    __nv_bfloat162 lb = __floats2bfloat162_rn(x - __bfloat162float(hb.x), y - __bfloat162float(hb.y));
    h = *(u32*)&hb; l = *(u32*)&lb;
}
__device__ __forceinline__ void stage_band(const float* __restrict__ src, char* Ah, char* Al, int R, int lane){
    #pragma unroll 4
    for (int i = 0; i < 16; ++i){
        int row = R + i;
        float4 v = ((const float4*)src)[row*32 + lane];
        u32 h0,l0,h1,l1; sp2(v.x,v.y,h0,l0); sp2(v.z,v.w,h1,l1);
        int o = row*PIT + lane*8;
        *(uint2*)(Ah+o) = make_uint2(h0,h1);
        *(uint2*)(Al+o) = make_uint2(l0,l1);
    }
}
__device__ __forceinline__ void wgemm3(float acc[16][4], u32 baseAh, u32 baseAl,
                                       u32 baseBh, u32 baseBl, int lane){
    u32 off = (lane & 15)*PIT + (lane >> 4)*16;
    #pragma unroll
    for (int ks = 0; ks < 8; ++ks){
        u32 ah[4], al[4];
        ldsm4(ah, baseAh + off + ks*32);
        ldsm4(al, baseAl + off + ks*32);
        #pragma unroll
        for (int nb = 0; nb < 8; ++nb){
            u32 bh[4], bl[4];
            u32 ba = off + ks*(16*PIT) + nb*32;
            ldsm4t(bh, baseBh + ba); ldsm4t(bl, baseBl + ba);
            mma_bf(acc[nb*2],   ah, bh[0], bh[1]);
            mma_bf(acc[nb*2],   ah, bl[0], bl[1]);
            mma_bf(acc[nb*2],   al, bh[0], bh[1]);
            mma_bf(acc[nb*2+1], ah, bh[2], bh[3]);
            mma_bf(acc[nb*2+1], ah, bl[2], bl[3]);
            mma_bf(acc[nb*2+1], al, bh[2], bh[3]);
        }
    }
}
__device__ __forceinline__ void zacc16(float acc[16][4]){
    #pragma unroll
    for (int i=0;i<16;++i){ acc[i][0]=0.f;acc[i][1]=0.f;acc[i][2]=0.f;acc[i][3]=0.f; }
}
__device__ __forceinline__ void write_mid(const float acc[16][4], const float* b1s,
                                          char* Ah, char* Al, int R, int lane){
    int r0 = R + (lane>>2), cb = (lane&3)*2;
    #pragma unroll
    for (int nb = 0; nb < 16; ++nb){
        int c = nb*8 + cb;
        float bx = b1s[c], by = b1s[c+1];
        u32 h0,l0,h1,l1;
        sp2(ssp(acc[nb][0]+bx), ssp(acc[nb][1]+by), h0, l0);
        sp2(ssp(acc[nb][2]+bx), ssp(acc[nb][3]+by), h1, l1);
        *(u32*)(Ah + r0*PIT + c*2) = h0;     *(u32*)(Al + r0*PIT + c*2) = l0;
        *(u32*)(Ah + (r0+8)*PIT + c*2) = h1; *(u32*)(Al + (r0+8)*PIT + c*2) = l1;
    }
}

__global__ void k_prep(const float* nlw, const float* ew1, const float* ew2,
                       const float* nw1, const float* nw2){
    const float* srcs[5] = {nlw, ew1, ew2, nw1, nw2};
    const float* src = srcs[blockIdx.x];
    int n = threadIdx.x;
    for (int k = 0; k < 128; ++k){
        float v = src[k*128 + n];
        __nv_bfloat16 h = __float2bfloat16_rn(v);
        __nv_bfloat16 l = __float2bfloat16_rn(v - __bfloat162float(h));
        *(__nv_bfloat16*)(g_Wimg[blockIdx.x][0] + k*256 + n*2) = h;
        *(__nv_bfloat16*)(g_Wimg[blockIdx.x][1] + k*256 + n*2) = l;
    }
}
__global__ void k_init_h(const int* __restrict__ charges, const float* __restrict__ emb){
    int idx = blockIdx.x*256 + threadIdx.x;
    g_h[idx] = emb[charges[idx>>7]*128 + (idx & 127)];
}
// RBF written directly as EA fragments; one warp per (m,d)
__global__ void k_init_ea(const float* __restrict__ coords){
    int gw = (blockIdx.x*256 + threadIdx.x) >> 5;
    int lane = threadIdx.x & 31;
    int m = gw / 24, d = gw % 24;
    int q = lane>>2, cp = lane&3;
    const float* cm = coords + (size_t)m*Aat*3;
    float ddx=cm[d*3], ddy=cm[d*3+1], ddz=cm[d*3+2];
    float dv[3];
    #pragma unroll
    for (int i=0;i<3;++i){
        int s = q + i*8;
        float ax=cm[s*3]-ddx, ay=cm[s*3+1]-ddy, az=cm[s*3+2]-ddz;
        dv[i] = sqrtf(ax*ax+ay*ay+az*az);
    }
    const float delta = 10.f/127.f, coeff = -0.5f/(delta*delta);
    u32* base = g_EAf + (size_t)gw*4096;
    #pragma unroll
    for (int ks=0; ks<8; ++ks){
        float c0 = (float)(16*ks + 2*cp);
        float v[3][4];
        #pragma unroll
        for (int i=0;i<3;++i)
            #pragma unroll
            for (int j=0;j<4;++j){
                float od = dv[i] - delta*(c0 + (float)((j>>1)*8 + (j&1)));
                v[i][j] = (fabsf(od) < 1.2f) ? __expf(coeff*od*od) : 0.f;
            }
        u32 h[4],l[4],h2[4],l2[4];
        sp2(v[0][0],v[0][1],h[0],l[0]); sp2(v[1][0],v[1][1],h[1],l[1]);
        sp2(v[0][2],v[0][3],h[2],l[2]); sp2(v[1][2],v[1][3],h[3],l[3]);
        sp2(v[2][0],v[2][1],h2[0],l2[0]); h2[1]=0; l2[1]=0;
        sp2(v[2][2],v[2][3],h2[2],l2[2]); h2[3]=0; l2[3]=0;
        u32* c = base + ks*512;
        *(uint4*)(c + lane*4)       = make_uint4(h[0],h[1],h[2],h[3]);
        *(uint4*)(c + 128 + lane*4) = make_uint4(h2[0],h2[1],h2[2],h2[3]);
        *(uint4*)(c + 256 + lane*4) = make_uint4(l[0],l[1],l[2],l[3]);
        *(uint4*)(c + 384 + lane*4) = make_uint4(l2[0],l2[1],l2[2],l2[3]);
    }
}

__global__ void __launch_bounds__(256,1) k_x_mma(){
    extern __shared__ __align__(16) char sm[];
    char *Wh = sm, *Wl = sm+IMG, *Ah = sm+2*IMG, *Al = sm+3*IMG;
    const int tid = threadIdx.x, wid = tid>>5, lane = tid&31, R = wid*16;
    for (int i = tid; i < 2048; i += 256){
        int k = i>>4, ch = i&15; u32 d = k*PIT + ch*16;
        cpa16(smaddr(Wh)+d, g_Wimg[0][0]+i*16);
        cpa16(smaddr(Wl)+d, g_Wimg[0][1]+i*16);
    }
    CP_COMMIT; CP_WAIT0; __syncthreads();
    size_t rowbase = (size_t)blockIdx.x * 128;
    stage_band(g_h + rowbase*128, Ah, Al, R, lane);
    __syncwarp();
    float acc[16][4]; zacc16(acc);
    wgemm3(acc, smaddr(Ah)+R*PIT, smaddr(Al)+R*PIT, smaddr(Wh), smaddr(Wl), lane);
    int r0 = (int)rowbase + R + (lane>>2), cb = (lane&3)*2;
    #pragma unroll
    for (int nb = 0; nb < 16; ++nb){
        int c = nb*8 + cb;
        *(float2*)(g_x + (size_t)r0*128 + c)     = make_float2(acc[nb][0], acc[nb][1]);
        *(float2*)(g_x + (size_t)(r0+8)*128 + c) = make_float2(acc[nb][2], acc[nb][3]);
    }
}

// edge kernel: warp owns one destination d (32 rows incl pad); EA in fragment layout
__global__ void __launch_bounds__(256,1) k_edge(const float* __restrict__ eb1, const float* __restrict__ eb2){
    extern __shared__ __align__(16) char sm[];
    char *W1h=sm, *W1l=sm+IMG, *W2h=sm+2*IMG, *W2l=sm+3*IMG;
    float* xs  = (float*)(sm+4*IMG);            // 32 x 132
    float* b1s = xs + 32*132; float* b2s = b1s + 128;
    const int tid=threadIdx.x, m=blockIdx.x;
    const int wid=tid>>5, lane=tid&31, q=lane>>2, cp=lane&3;
    for (int i=tid;i<2048;i+=256){
        int k=i>>4, ch=i&15; u32 dof=k*PIT+ch*16;
        cpa16(smaddr(W1h)+dof, g_Wimg[1][0]+i*16);
        cpa16(smaddr(W1l)+dof, g_Wimg[1][1]+i*16);
        cpa16(smaddr(W2h)+dof, g_Wimg[2][0]+i*16);
        cpa16(smaddr(W2l)+dof, g_Wimg[2][1]+i*16);
    }
    CP_COMMIT;
    for (int i=tid;i<Aat*128;i+=256) xs[(i>>7)*132+(i&127)] = g_x[(size_t)m*3072+i];
    for (int i=tid;i<8*132;i+=256) xs[24*132+i]=0.f;
    if (tid<128){ b1s[tid]=eb1[tid]; b2s[tid]=eb2[tid]; }
    CP_WAIT0; __syncthreads();

    const u32 sW1h=smaddr(W1h), sW1l=smaddr(W1l), sW2h=smaddr(W2h), sW2l=smaddr(W2l);
    const u32 loff = (lane&15)*PIT + (lane>>4)*16;

    for (int pass=0; pass<3; ++pass){
        const int d = pass*8 + wid;
        u32* base = g_EAf + ((size_t)(m*24+d))*4096;

        float acc1[2][16][4];
        zacc16(acc1[0]); zacc16(acc1[1]);
        uint4 H0=*(const uint4*)(base+lane*4),     H1=*(const uint4*)(base+128+lane*4);
        uint4 L0=*(const uint4*)(base+256+lane*4), L1=*(const uint4*)(base+384+lane*4);
        #pragma unroll
        for (int ks=0;ks<8;++ks){
            uint4 nH0,nH1,nL0,nL1;
            if (ks<7){
                const u32* nb = base+(ks+1)*512;
                nH0=*(const uint4*)(nb+lane*4);     nH1=*(const uint4*)(nb+128+lane*4);
                nL0=*(const uint4*)(nb+256+lane*4); nL1=*(const uint4*)(nb+384+lane*4);
            }
            u32 ah0[4]={H0.x,H0.y,H0.z,H0.w}, ah1[4]={H1.x,H1.y,H1.z,H1.w};
            u32 al0[4]={L0.x,L0.y,L0.z,L0.w}, al1[4]={L1.x,L1.y,L1.z,L1.w};
            #pragma unroll
            for (int j=0;j<8;++j){
                u32 bh[4],bl[4]; u32 ba=loff+ks*(16*PIT)+j*32;
                ldsm4t(bh,sW1h+ba); ldsm4t(bl,sW1l+ba);
                mma_bf(acc1[0][2*j],   ah0,bh[0],bh[1]); mma_bf(acc1[0][2*j],   ah0,bl[0],bl[1]); mma_bf(acc1[0][2*j],   al0,bh[0],bh[1]);
                mma_bf(acc1[0][2*j+1], ah0,bh[2],bh[3]); mma_bf(acc1[0][2*j+1], ah0,bl[2],bl[3]); mma_bf(acc1[0][2*j+1], al0,bh[2],bh[3]);
                mma_bf(acc1[1][2*j],   ah1,bh[0],bh[1]); mma_bf(acc1[1][2*j],   ah1,bl[0],bl[1]); mma_bf(acc1[1][2*j],   al1,bh[0],bh[1]);
                mma_bf(acc1[1][2*j+1], ah1,bh[2],bh[3]); mma_bf(acc1[1][2*j+1], ah1,bl[2],bl[3]); mma_bf(acc1[1][2*j+1], al1,bh[2],bh[3]);
            }
            if (ks<7){ H0=nH0; H1=nH1; L0=nL0; L1=nL1; }
        }
        // mid = ssp(acc1+b1) -> A2 fragments (C-layout == A-layout identity)
        u32 a2h[2][8][4], a2l[2][8][4];
        #pragma unroll
        for (int mb=0;mb<2;++mb)
            #pragma unroll
            for (int j=0;j<8;++j){
                int c0=16*j+2*cp;
                float bA0=b1s[c0], bA1=b1s[c0+1], bB0=b1s[c0+8], bB1=b1s[c0+9];
                sp2(ssp(acc1[mb][2*j][0]+bA0),   ssp(acc1[mb][2*j][1]+bA1),   a2h[mb][j][0], a2l[mb][j][0]);
                sp2(ssp(acc1[mb][2*j][2]+bA0),   ssp(acc1[mb][2*j][3]+bA1),   a2h[mb][j][1], a2l[mb][j][1]);
                sp2(ssp(acc1[mb][2*j+1][0]+bB0), ssp(acc1[mb][2*j+1][1]+bB1), a2h[mb][j][2], a2l[mb][j][2]);
                sp2(ssp(acc1[mb][2*j+1][2]+bB0), ssp(acc1[mb][2*j+1][3]+bB1), a2h[mb][j][3], a2l[mb][j][3]);
            }
        // GEMM2 in two N-halves + fused epilogue (store frags + shuffle agg)
        #pragma unroll
        for (int hf=0; hf<2; ++hf){
            float acc2[2][8][4];
            zacc16(*(float(*)[16][4])&acc2[0][0][0]);
            #pragma unroll
            for (int ks=0;ks<8;++ks)
                #pragma unroll
                for (int j=0;j<4;++j){
                    u32 bh[4],bl[4]; u32 ba=loff+ks*(16*PIT)+(hf*4+j)*32;
                    ldsm4t(bh,sW2h+ba); ldsm4t(bl,sW2l+ba);
                    #pragma unroll
                    for (int mb=0;mb<2;++mb){
                        mma_bf(acc2[mb][2*j],   a2h[mb][ks],bh[0],bh[1]);
                        mma_bf(acc2[mb][2*j],   a2h[mb][ks],bl[0],bl[1]);
                        mma_bf(acc2[mb][2*j],   a2l[mb][ks],bh[0],bh[1]);
                        mma_bf(acc2[mb][2*j+1], a2h[mb][ks],bh[2],bh[3]);
                        mma_bf(acc2[mb][2*j+1], a2h[mb][ks],bl[2],bl[3]);
                        mma_bf(acc2[mb][2*j+1], a2l[mb][ks],bh[2],bh[3]);
                    }
                }
            float wag[4][4];
            #pragma unroll
            for (int j=0;j<4;++j){ wag[j][0]=0;wag[j][1]=0;wag[j][2]=0;wag[j][3]=0; }
            #pragma unroll
            for (int mb=0;mb<2;++mb){
                int s0=mb*16+q, s1=s0+8;
                bool k0=(s0<24)&&(s0!=d), k1=(s1<24)&&(s1!=d);
                #pragma unroll
                for (int j=0;j<4;++j){
                    int cA=hf*64+16*j+2*cp, cB=cA+8;
                    float bA0=b2s[cA],bA1=b2s[cA+1],bB0=b2s[cB],bB1=b2s[cB+1];
                    float v00=(acc2[mb][2*j][0]+bA0)*xs[s0*132+cA];
                    float v01=(acc2[mb][2*j][1]+bA1)*xs[s0*132+cA+1];
                    float v10=(acc2[mb][2*j][2]+bA0)*xs[s1*132+cA];
                    float v11=(acc2[mb][2*j][3]+bA1)*xs[s1*132+cA+1];
                    float w00=(acc2[mb][2*j+1][0]+bB0)*xs[s0*132+cB];
                    float w01=(acc2[mb][2*j+1][1]+bB1)*xs[s0*132+cB+1];
                    float w10=(acc2[mb][2*j+1][2]+bB0)*xs[s1*132+cB];
                    float w11=(acc2[mb][2*j+1][3]+bB1)*xs[s1*132+cB+1];
                    if(k0){ wag[j][0]+=v00; wag[j][1]+=v01; wag[j][2]+=w00; wag[j][3]+=w01; }
                    if(k1){ wag[j][0]+=v10; wag[j][1]+=v11; wag[j][2]+=w10; wag[j][3]+=w11; }
                    u32 h4[4],l4[4];
                    sp2(v00,v01,h4[0],l4[0]); sp2(v10,v11,h4[1],l4[1]);
                    sp2(w00,w01,h4[2],l4[2]); sp2(w10,w11,h4[3],l4[3]);
                    u32* c = base + (hf*4+j)*512 + mb*128;
                    *(uint4*)(c+lane*4)     = make_uint4(h4[0],h4[1],h4[2],h4[3]);
                    *(uint4*)(c+256+lane*4) = make_uint4(l4[0],l4[1],l4[2],l4[3]);
                }
            }
            #pragma unroll
            for (int j=0;j<4;++j){
                #pragma unroll
                for (int u2=0;u2<4;++u2){
                    float t=wag[j][u2];
                    t += __shfl_xor_sync(~0u,t,4); t += __shfl_xor_sync(~0u,t,8); t += __shfl_xor_sync(~0u,t,16);
                    wag[j][u2]=t;
                }
                if (lane<4){
                    int cA=hf*64+16*j+2*lane;
                    float* ag = g_agg + ((size_t)(m*24+d))*128;
                    *(float2*)&ag[cA]   = make_float2(wag[j][0],wag[j][1]);
                    *(float2*)&ag[cA+8] = make_float2(wag[j][2],wag[j][3]);
                }
            }
        }
    }
}

__global__ void __launch_bounds__(256,1) k_node_mma(const float* __restrict__ nb1, const float* __restrict__ nb2){
    extern __shared__ __align__(16) char sm[];
    char *W1h = sm, *W1l = sm+IMG, *W2h = sm+2*IMG, *W2l = sm+3*IMG;
    char *Ah = sm+4*IMG, *Al = sm+5*IMG;
    float* b1s = (float*)(sm + 6*IMG); float* b2s = b1s + 128;
    const int tid = threadIdx.x, wid = tid>>5, lane = tid&31, R = wid*16;
    for (int i = tid; i < 2048; i += 256){
        int k = i>>4, ch = i&15; u32 d = k*PIT + ch*16;
        cpa16(smaddr(W1h)+d, g_Wimg[3][0]+i*16);
        cpa16(smaddr(W1l)+d, g_Wimg[3][1]+i*16);
        cpa16(smaddr(W2h)+d, g_Wimg[4][0]+i*16);
        cpa16(smaddr(W2l)+d, g_Wimg[4][1]+i*16);
    }
    CP_COMMIT;
    if (tid < 128){ b1s[tid] = nb1[tid]; b2s[tid] = nb2[tid]; }
    CP_WAIT0; __syncthreads();
    size_t rowbase = (size_t)blockIdx.x * 128;
    stage_band(g_agg + rowbase*128, Ah, Al, R, lane);
    __syncwarp();
    float acc[16][4]; zacc16(acc);
    wgemm3(acc, smaddr(Ah)+R*PIT, smaddr(Al)+R*PIT, smaddr(W1h), smaddr(W1l), lane);
    write_mid(acc, b1s, Ah, Al, R, lane);
    __syncwarp();
    zacc16(acc);
    wgemm3(acc, smaddr(Ah)+R*PIT, smaddr(Al)+R*PIT, smaddr(W2h), smaddr(W2l), lane);
    int r0 = (int)rowbase + R + (lane>>2), cb = (lane&3)*2;
    #pragma unroll
    for (int nb = 0; nb < 16; ++nb){
        int c = nb*8 + cb;
        float bx = b2s[c], by = b2s[c+1];
        float2 h0 = *(float2*)(g_h + (size_t)r0*128 + c);
        float2 h1 = *(float2*)(g_h + (size_t)(r0+8)*128 + c);
        h0.x += acc[nb][0] + bx;  h0.y += acc[nb][1] + by;
        h1.x += acc[nb][2] + bx;  h1.y += acc[nb][3] + by;
        *(float2*)(g_h + (size_t)r0*128 + c)     = h0;
        *(float2*)(g_h + (size_t)(r0+8)*128 + c) = h1;
    }
}

__global__ void __launch_bounds__(256) k_graph(const float* __restrict__ gw1, const float* __restrict__ gb1,
                                               const float* __restrict__ gw2, const float* __restrict__ gb2,
                                               float* __restrict__ out)
{
    __shared__ float hs[Aat*128];
    __shared__ float w1s[128*64];
    __shared__ float red[256];
    const int tid = threadIdx.x, m = blockIdx.x;
    {
        const float4* hg = (const float4*)(g_h + (size_t)m*Aat*128);
        for (int i = tid; i < 768; i += 256) ((float4*)hs)[i] = hg[i];
        const float4* wg = (const float4*)gw1;
        for (int i = tid; i < 2048; i += 256) ((float4*)w1s)[i] = wg[i];
    }
    __syncthreads();
    float local = 0.f;
    for (int pos = tid; pos < Aat*64; pos += 256){
        int s = pos >> 6, c = pos & 63;
        float acc = gb1[c];
        #pragma unroll 16
        for (int k = 0; k < 128; ++k) acc += hs[s*128+k] * w1s[k*64+c];
        local += ssp(acc) * gw2[c];
    }
    red[tid] = local;
    __syncthreads();
    #pragma unroll
    for (int off = 128; off > 0; off >>= 1){
        if (tid < off) red[tid] += red[tid+off];
        __syncthreads();
    }
    if (tid == 0) out[m] = red[0] + (float)Aat * gb2[0];
}

extern "C" void kernel_launch(void* const* d_in, const int* in_sizes, int n_in,
                              void* d_out, int out_size)
{
    const int*   charges = (const int*)  d_in[0];
    const float* coords  = (const float*)d_in[1];
    const float* emb = (const float*)d_in[4];
    const float* nlw = (const float*)d_in[5];
    const float* ew1 = (const float*)d_in[6];
    const float* eb1 = (const float*)d_in[7];
    const float* ew2 = (const float*)d_in[8];
    const float* eb2 = (const float*)d_in[9];
    const float* nw1 = (const float*)d_in[10];
    const float* nb1 = (const float*)d_in[11];
    const float* nw2 = (const float*)d_in[12];
    const float* nb2 = (const float*)d_in[13];
    const float* gw1 = (const float*)d_in[14];
    const float* gb1 = (const float*)d_in[15];
    const float* gw2 = (const float*)d_in[16];
    const float* gb2 = (const float*)d_in[17];
    float* out = (float*)d_out;

    const int SME = 4*IMG + 32*132*4 + 1024;   // 157184
    const int SMN = 6*IMG + 1024;              // 209920
    const int SMX = 4*IMG;                     // 139264
    cudaFuncSetAttribute(k_edge,     cudaFuncAttributeMaxDynamicSharedMemorySize, SME);
    cudaFuncSetAttribute(k_node_mma, cudaFuncAttributeMaxDynamicSharedMemorySize, SMN);
    cudaFuncSetAttribute(k_x_mma,    cudaFuncAttributeMaxDynamicSharedMemorySize, SMX);

    k_prep<<<5, 128>>>(nlw, ew1, ew2, nw1, nw2);
    k_init_h <<<(Nnode*128)/256, 256>>>(charges, emb);
    k_init_ea<<<(Mmol*24)/8, 256>>>(coords);

    for (int l = 0; l < 4; ++l) {
        k_x_mma   <<<384,  256, SMX>>>();
        k_edge    <<<Mmol, 256, SME>>>(eb1, eb2);
        k_node_mma<<<384,  256, SMN>>>(nb1, nb2);
    }
    k_graph<<<Mmol, 256>>>(gw1, gb1, gw2, gb2, out);
}